// round 6
// baseline (speedup 1.0000x reference)
#include <cuda_runtime.h>
#include <cstdint>

// Problem constants
constexpr int Qn = 128;      // slices
constexpr int Sn = 128;      // slice length (K)
constexpr int Hn = 32;       // hidden (N)
constexpr int Cn = Qn * Sn;  // 16384 channels
constexpr int MT = 64;       // batch rows per tile

// SMEM layout in floats.
// A double-buffered; raw B and cons B single-buffered (see pipeline order).
constexpr int AS = 132;       // A row stride: bank(132r+k)=(4r+k)%32, conflict-free a-frags
constexpr int RS = 40;        // raw B row stride: makes gather LDS.32 conflict-free
constexpr int A_STAGE  = MT * AS;              // 8448 floats per A stage
constexpr int OFF_A    = 0;                    // A0 @0, A1 @8448
constexpr int OFF_BIAS = 2 * A_STAGE;          // 2 stages x 68 (b1[32],W2[32],b2,pad)
constexpr int OFF_RAW  = OFF_BIAS + 2 * 68;    // 17032: raw B [128][40] = 5120
constexpr int OFF_CONS = OFF_RAW + Sn * RS;    // 22152: cons B 4096 floats
constexpr int SMEM_FLOATS = OFF_CONS + Sn * Hn;   // 26248
constexpr int SMEM_BYTES  = SMEM_FLOATS * 4;      // 104992 B -> 2 CTAs/SM
constexpr int GRID = 296;    // 2 CTAs x 148 SMs, all resident

static __device__ __forceinline__ uint32_t smem_u32(const void* p) {
    uint32_t a;
    asm("{ .reg .u64 t; cvta.to.shared.u64 t, %1; cvt.u32.u64 %0, t; }" : "=r"(a) : "l"(p));
    return a;
}

static __device__ __forceinline__ uint32_t tf32rna(float f) {
    uint32_t r;
    asm("cvt.rna.tf32.f32 %0, %1;" : "=r"(r) : "f"(f));
    return r;
}

#define CP16(dst, src) \
    asm volatile("cp.async.cg.shared.global [%0], [%1], 16;" :: "r"(dst), "l"(src))
#define CP4(dst, src) \
    asm volatile("cp.async.ca.shared.global [%0], [%1], 4;" :: "r"(dst), "l"(src))

static __device__ __forceinline__ void mma_tf32(
    float& c0, float& c1, float& c2, float& c3,
    uint32_t a0, uint32_t a1, uint32_t a2, uint32_t a3,
    uint32_t b0, uint32_t b1)
{
    asm volatile(
        "mma.sync.aligned.m16n8k8.row.col.f32.tf32.tf32.f32 "
        "{%0,%1,%2,%3}, {%4,%5,%6,%7}, {%8,%9}, {%0,%1,%2,%3};"
        : "+f"(c0), "+f"(c1), "+f"(c2), "+f"(c3)
        : "r"(a0), "r"(a1), "r"(a2), "r"(a3), "r"(b0), "r"(b1));
}

// Prefetch tile (mt,q): A+bias into stage s, raw B into the single raw buffer.
static __device__ __forceinline__ void prefetch_tile(
    uint32_t sb, int s, int tile, int tid,
    const float* __restrict__ x,  const float* __restrict__ W1,
    const float* __restrict__ b1, const float* __restrict__ W2,
    const float* __restrict__ b2)
{
    const int q  = tile & (Qn - 1);
    const int mt = tile >> 7;

    // A: x tile [64 rows x 128 K] -> [64][132] floats in stage s
    const float* xb = x + (size_t)(mt * MT) * Cn + (size_t)q * Sn;
    const uint32_t dA = sb + (OFF_A + s * A_STAGE) * 4;
    #pragma unroll
    for (int i = 0; i < 16; i++) {
        int idx = i * 128 + tid;       // 2048 16B chunks
        int r   = idx >> 5;
        int c4  = idx & 31;
        CP16(dA + r * (AS * 4) + c4 * 16, xb + (size_t)r * Cn + c4 * 4);
    }

    // raw B: W1[q] [128 k x 32 n] -> [128][40] floats (single buffer)
    const float* w1 = W1 + (size_t)q * Sn * Hn;
    const uint32_t dB = sb + OFF_RAW * 4;
    #pragma unroll
    for (int i = 0; i < 8; i++) {
        int idx = i * 128 + tid;       // 1024 16B chunks
        int k  = idx >> 3;
        int h4 = idx & 7;
        CP16(dB + k * (RS * 4) + h4 * 16, w1 + k * Hn + h4 * 4);
    }

    // Biases into stage s: b1[32], W2[32], b2[1]
    const uint32_t dBias = sb + (OFF_BIAS + s * 68) * 4;
    if (tid < 16) {
        const float* src = (tid < 8) ? (b1 + q * Hn + tid * 4)
                                     : (W2 + q * Hn + (tid - 8) * 4);
        CP16(dBias + tid * 16, src);
    } else if (tid == 16) {
        CP4(dBias + 64 * 4, b2 + q);
    }
    asm volatile("cp.async.commit_group;" ::: "memory");
}

__global__ void __launch_bounds__(128, 2) divenc_kernel(
    const float* __restrict__ x,   // [B, C]
    const float* __restrict__ W1,  // [Q, S, H]
    const float* __restrict__ b1,  // [Q, H]
    const float* __restrict__ W2,  // [Q, H]
    const float* __restrict__ b2,  // [Q]
    float* __restrict__ out,       // [B, Q]
    int ntiles)
{
    extern __shared__ float sm[];
    const uint32_t sb = smem_u32(sm);
    const int tid  = threadIdx.x;
    const int wid  = tid >> 5;
    const int lane = tid & 31;
    const int g    = lane >> 2;    // fragment row
    const int t    = lane & 3;     // fragment col quad

    int tile = blockIdx.x;
    if (tile >= ntiles) return;

    // Prologue prefetch
    prefetch_tile(sb, 0, tile, tid, x, W1, b1, W2, b2);

    int s = 0;
    for (; tile < ntiles; tile += GRID) {
        // Everything issued so far (prefetch of this tile) must be resident.
        asm volatile("cp.async.wait_group 0;" ::: "memory");
        __syncthreads();

        // ---- Gather: raw B [k][40] -> consumption-order cons (float4 per lane) ----
        // cons[(ks*2+h)*32 + l] = { W[k][n0], W[k][n0+8], W[k][n0+16], W[k][n0+24] }
        //   with k = ks*8 + h*4 + (l&3), n0 = l>>2.  Conflict-free on both ends.
        {
            const float* raw = sm + OFF_RAW;
            float4* cons = reinterpret_cast<float4*>(sm + OFF_CONS);
            #pragma unroll
            for (int r = 0; r < 8; r++) {
                int c  = r * 128 + tid;
                int lf = c & 31;
                int k  = ((c >> 6) * 8) + (((c >> 5) & 1) * 4) + (lf & 3);
                int n0 = lf >> 2;
                const float* rk = raw + k * RS + n0;
                float4 v;
                v.x = rk[0];
                v.y = rk[8];
                v.z = rk[16];
                v.w = rk[24];
                cons[c] = v;
            }
        }
        __syncthreads();

        // ---- Issue prefetch of next tile (A -> stage s^1, B -> raw) ----
        const int tn = tile + GRID;
        if (tn < ntiles)
            prefetch_tile(sb, s ^ 1, tn, tid, x, W1, b1, W2, b2);

        const float* sA    = sm + OFF_A + s * A_STAGE;
        const float* sBias = sm + OFF_BIAS + s * 68;

        // ---- MMA: warp computes M=16 x N=32 x K=128 ----
        float c[4][4];
        #pragma unroll
        for (int nf = 0; nf < 4; nf++)
            #pragma unroll
            for (int e = 0; e < 4; e++) c[nf][e] = 0.0f;

        const int mbase = wid * 16;
        const float* arow0 = sA + (mbase + g) * AS + t;
        const float* arow1 = arow0 + 8 * AS;
        const float4* bfr = reinterpret_cast<const float4*>(sm + OFF_CONS) + lane;

        #pragma unroll
        for (int ks = 0; ks < 16; ks++) {
            const int k0 = ks * 8;
            uint32_t a0 = tf32rna(arow0[k0]);
            uint32_t a1 = tf32rna(arow1[k0]);
            uint32_t a2 = tf32rna(arow0[k0 + 4]);
            uint32_t a3 = tf32rna(arow1[k0 + 4]);
            float4 bh0 = bfr[(ks * 2 + 0) * 32];   // b0 for nf=0..3
            float4 bh1 = bfr[(ks * 2 + 1) * 32];   // b1 for nf=0..3
            const float* b0p = reinterpret_cast<const float*>(&bh0);
            const float* b1p = reinterpret_cast<const float*>(&bh1);
            #pragma unroll
            for (int nf = 0; nf < 4; nf++) {
                mma_tf32(c[nf][0], c[nf][1], c[nf][2], c[nf][3],
                         a0, a1, a2, a3,
                         __float_as_uint(b0p[nf]), __float_as_uint(b1p[nf]));
            }
        }

        // ---- Epilogue: +b1, ELU, dot W2, +b2, quad-reduce, store ----
        const int q  = tile & (Qn - 1);
        const int mt = tile >> 7;
        const float bias2 = sBias[64];
        float pA = 0.0f, pB = 0.0f;   // rows mbase+g, mbase+g+8
        #pragma unroll
        for (int nf = 0; nf < 4; nf++) {
            #pragma unroll
            for (int e = 0; e < 2; e++) {
                const int col = nf * 8 + 2 * t + e;
                const float w2c = sBias[32 + col];
                const float b1c = sBias[col];
                float vA = c[nf][e] + b1c;
                float vB = c[nf][2 + e] + b1c;
                vA = (vA > 0.0f) ? vA : (__expf(fminf(vA, 0.0f)) - 1.0f);
                vB = (vB > 0.0f) ? vB : (__expf(fminf(vB, 0.0f)) - 1.0f);
                pA = fmaf(vA, w2c, pA);
                pB = fmaf(vB, w2c, pB);
            }
        }
        pA += __shfl_xor_sync(0xFFFFFFFFu, pA, 1);
        pA += __shfl_xor_sync(0xFFFFFFFFu, pA, 2);
        pB += __shfl_xor_sync(0xFFFFFFFFu, pB, 1);
        pB += __shfl_xor_sync(0xFFFFFFFFu, pB, 2);
        if (t == 0) {
            const int m = mt * MT + mbase + g;
            out[(size_t)m * Qn + q]       = pA + bias2;
            out[(size_t)(m + 8) * Qn + q] = pB + bias2;
        }
        s ^= 1;
    }
}

extern "C" void kernel_launch(void* const* d_in, const int* in_sizes, int n_in,
                              void* d_out, int out_size) {
    const float* x  = (const float*)d_in[0];
    const float* W1 = (const float*)d_in[1];
    const float* b1 = (const float*)d_in[2];
    const float* W2 = (const float*)d_in[3];
    const float* b2 = (const float*)d_in[4];
    float* out = (float*)d_out;

    const int B = in_sizes[0] / Cn;            // 2048
    const int ntiles = (B / MT) * Qn;          // 4096

    static bool configured = false;
    if (!configured) {
        cudaFuncSetAttribute(divenc_kernel,
                             cudaFuncAttributeMaxDynamicSharedMemorySize, SMEM_BYTES);
        configured = true;
    }
    divenc_kernel<<<GRID, 128, SMEM_BYTES>>>(x, W1, b1, W2, b2, out, ntiles);
}

// round 9
// speedup vs baseline: 1.0855x; 1.0855x over previous
#include <cuda_runtime.h>
#include <cstdint>

// Problem constants
constexpr int Qn = 128;      // slices
constexpr int Sn = 128;      // slice length (K)
constexpr int Hn = 32;       // hidden (N)
constexpr int Cn = Qn * Sn;  // 16384 channels
constexpr int MT = 64;       // batch rows per tile

// SMEM layout in floats, double buffered (identical to the 38.9us R3 kernel).
constexpr int AS = 132;                    // A row stride: bank(132r+k)=(4r+k)%32 -> conflict-free a-frags
constexpr int BS = 40;                     // B row stride: bank(40k+n)=(8k+n)%32 -> conflict-free b-frags
constexpr int OFF_A    = 0;                // A: [64][132]
constexpr int OFF_B    = OFF_A + MT * AS;  // B: [128][40] (k-major, n contiguous)
constexpr int OFF_BIAS = OFF_B + Sn * BS;  // b1[32], W2[32], b2[1]
constexpr int STAGE = 13648;               // floats per stage (16B aligned)
constexpr int SMEM_BYTES = 2 * STAGE * 4;  // 109184 B -> 2 CTAs/SM
constexpr int GRID = 296;                  // 2 CTAs x 148 SMs, all resident

static __device__ __forceinline__ uint32_t smem_u32(const void* p) {
    uint32_t a;
    asm("{ .reg .u64 t; cvta.to.shared.u64 t, %1; cvt.u32.u64 %0, t; }" : "=r"(a) : "l"(p));
    return a;
}

static __device__ __forceinline__ uint32_t tf32rna(float f) {
    uint32_t r;
    asm("cvt.rna.tf32.f32 %0, %1;" : "=r"(r) : "f"(f));
    return r;
}

#define CP16(dst, src) \
    asm volatile("cp.async.cg.shared.global [%0], [%1], 16;" :: "r"(dst), "l"(src))
#define CP4(dst, src) \
    asm volatile("cp.async.ca.shared.global [%0], [%1], 4;" :: "r"(dst), "l"(src))

static __device__ __forceinline__ void mma_tf32(
    float& c0, float& c1, float& c2, float& c3,
    uint32_t a0, uint32_t a1, uint32_t a2, uint32_t a3,
    uint32_t b0, uint32_t b1)
{
    asm volatile(
        "mma.sync.aligned.m16n8k8.row.col.f32.tf32.tf32.f32 "
        "{%0,%1,%2,%3}, {%4,%5,%6,%7}, {%8,%9}, {%0,%1,%2,%3};"
        : "+f"(c0), "+f"(c1), "+f"(c2), "+f"(c3)
        : "r"(a0), "r"(a1), "r"(a2), "r"(a3), "r"(b0), "r"(b1));
}

// Prefetch tile (mt,q) into stage s via cp.async (one commit group).
static __device__ __forceinline__ void prefetch_tile(
    uint32_t sb, int s, int tile, int tid,
    const float* __restrict__ x,  const float* __restrict__ W1,
    const float* __restrict__ b1, const float* __restrict__ W2,
    const float* __restrict__ b2)
{
    const int q  = tile & (Qn - 1);
    const int mt = tile >> 7;
    const uint32_t base = sb + (uint32_t)s * (STAGE * 4);

    // A: x tile [64 rows x 128 K] -> [64][132] floats
    const float* xb = x + (size_t)(mt * MT) * Cn + (size_t)q * Sn;
    const uint32_t dA = base + OFF_A * 4;
    #pragma unroll
    for (int i = 0; i < 16; i++) {
        int idx = i * 128 + tid;       // 2048 16B chunks
        int r   = idx >> 5;
        int c4  = idx & 31;
        CP16(dA + r * (AS * 4) + c4 * 16, xb + (size_t)r * Cn + c4 * 4);
    }

    // B: W1[q] [128 k x 32 n] raw -> [128][40] floats
    const float* w1 = W1 + (size_t)q * Sn * Hn;
    const uint32_t dB = base + OFF_B * 4;
    #pragma unroll
    for (int i = 0; i < 8; i++) {
        int idx = i * 128 + tid;       // 1024 16B chunks
        int k  = idx >> 3;
        int h4 = idx & 7;
        CP16(dB + k * (BS * 4) + h4 * 16, w1 + k * Hn + h4 * 4);
    }

    // Biases: b1[32], W2[32], b2[1]
    const uint32_t dBias = base + OFF_BIAS * 4;
    if (tid < 16) {
        const float* src = (tid < 8) ? (b1 + q * Hn + tid * 4)
                                     : (W2 + q * Hn + (tid - 8) * 4);
        CP16(dBias + tid * 16, src);
    } else if (tid == 16) {
        CP4(dBias + 64 * 4, b2 + q);
    }
    asm volatile("cp.async.commit_group;" ::: "memory");
}

__global__ void __launch_bounds__(128, 2) divenc_kernel(
    const float* __restrict__ x,   // [B, C]
    const float* __restrict__ W1,  // [Q, S, H]
    const float* __restrict__ b1,  // [Q, H]
    const float* __restrict__ W2,  // [Q, H]
    const float* __restrict__ b2,  // [Q]
    float* __restrict__ out,       // [B, Q]
    int ntiles)
{
    extern __shared__ float sm[];
    const uint32_t sb = smem_u32(sm);
    const int tid  = threadIdx.x;
    const int wid  = tid >> 5;
    const int lane = tid & 31;
    const int g    = lane >> 2;    // fragment row
    const int t    = lane & 3;     // fragment col quad

    int tile = blockIdx.x;
    if (tile >= ntiles) return;

    // Prologue prefetch
    prefetch_tile(sb, 0, tile, tid, x, W1, b1, W2, b2);

    int s = 0;
    for (; tile < ntiles; tile += GRID) {
        const int tn = tile + GRID;
        if (tn < ntiles) {
            prefetch_tile(sb, s ^ 1, tn, tid, x, W1, b1, W2, b2);
            asm volatile("cp.async.wait_group 1;" ::: "memory");
        } else {
            asm volatile("cp.async.wait_group 0;" ::: "memory");
        }
        __syncthreads();

        const float* sA = sm + s * STAGE + OFF_A;
        const float* sB = sm + s * STAGE + OFF_B;
        const float* sBias = sm + s * STAGE + OFF_BIAS;

        // ---- MMA: warp computes M=16 x N=32 x K=128 ----
        // Even/odd ping-pong software pipeline: while MMAs for one parity
        // issue, the other parity's fragments are being loaded from smem,
        // giving the LDS a full half-iteration (~20+ instrs) of cover.
        float c[4][4];
        #pragma unroll
        for (int nf = 0; nf < 4; nf++)
            #pragma unroll
            for (int e = 0; e < 4; e++) c[nf][e] = 0.0f;

        const int mbase = wid * 16;
        const float* arow0 = sA + (mbase + g) * AS + t;
        const float* arow1 = arow0 + 8 * AS;
        const float* brow  = sB + t * BS;          // + k0*BS + n

        float aE[4], bE0[4], bE1[4];   // even-ks fragments
        float aO[4], bO0[4], bO1[4];   // odd-ks fragments

        // Preload ks=0 into the even set.
        aE[0] = arow0[0];
        aE[1] = arow1[0];
        aE[2] = arow0[4];
        aE[3] = arow1[4];
        #pragma unroll
        for (int nf = 0; nf < 4; nf++) {
            const int n = nf * 8 + g;
            bE0[nf] = brow[n];
            bE1[nf] = brow[4 * BS + n];
        }

        #pragma unroll
        for (int ks = 0; ks < 16; ks += 2) {
            // Load odd (ks+1) while even (ks) computes.
            {
                const int k1 = (ks + 1) * 8;
                aO[0] = arow0[k1];
                aO[1] = arow1[k1];
                aO[2] = arow0[k1 + 4];
                aO[3] = arow1[k1 + 4];
                #pragma unroll
                for (int nf = 0; nf < 4; nf++) {
                    const int n = nf * 8 + g;
                    bO0[nf] = brow[k1 * BS + n];
                    bO1[nf] = brow[(k1 + 4) * BS + n];
                }
            }
            {
                const uint32_t a0 = tf32rna(aE[0]);
                const uint32_t a1 = tf32rna(aE[1]);
                const uint32_t a2 = tf32rna(aE[2]);
                const uint32_t a3 = tf32rna(aE[3]);
                #pragma unroll
                for (int nf = 0; nf < 4; nf++)
                    mma_tf32(c[nf][0], c[nf][1], c[nf][2], c[nf][3],
                             a0, a1, a2, a3,
                             __float_as_uint(bE0[nf]), __float_as_uint(bE1[nf]));
            }
            // Load even (ks+2) while odd (ks+1) computes.
            if (ks + 2 < 16) {
                const int k2 = (ks + 2) * 8;
                aE[0] = arow0[k2];
                aE[1] = arow1[k2];
                aE[2] = arow0[k2 + 4];
                aE[3] = arow1[k2 + 4];
                #pragma unroll
                for (int nf = 0; nf < 4; nf++) {
                    const int n = nf * 8 + g;
                    bE0[nf] = brow[k2 * BS + n];
                    bE1[nf] = brow[(k2 + 4) * BS + n];
                }
            }
            {
                const uint32_t a0 = tf32rna(aO[0]);
                const uint32_t a1 = tf32rna(aO[1]);
                const uint32_t a2 = tf32rna(aO[2]);
                const uint32_t a3 = tf32rna(aO[3]);
                #pragma unroll
                for (int nf = 0; nf < 4; nf++)
                    mma_tf32(c[nf][0], c[nf][1], c[nf][2], c[nf][3],
                             a0, a1, a2, a3,
                             __float_as_uint(bO0[nf]), __float_as_uint(bO1[nf]));
            }
        }

        // ---- Epilogue: +b1, ELU, dot W2, +b2, quad-reduce, store ----
        const int q  = tile & (Qn - 1);
        const int mt = tile >> 7;
        const float bias2 = sBias[64];
        float pA = 0.0f, pB = 0.0f;   // rows mbase+g, mbase+g+8
        #pragma unroll
        for (int nf = 0; nf < 4; nf++) {
            #pragma unroll
            for (int e = 0; e < 2; e++) {
                const int col = nf * 8 + 2 * t + e;
                const float w2c = sBias[32 + col];
                const float b1c = sBias[col];
                float vA = c[nf][e] + b1c;
                float vB = c[nf][2 + e] + b1c;
                vA = (vA > 0.0f) ? vA : (__expf(fminf(vA, 0.0f)) - 1.0f);
                vB = (vB > 0.0f) ? vB : (__expf(fminf(vB, 0.0f)) - 1.0f);
                pA = fmaf(vA, w2c, pA);
                pB = fmaf(vB, w2c, pB);
            }
        }
        pA += __shfl_xor_sync(0xFFFFFFFFu, pA, 1);
        pA += __shfl_xor_sync(0xFFFFFFFFu, pA, 2);
        pB += __shfl_xor_sync(0xFFFFFFFFu, pB, 1);
        pB += __shfl_xor_sync(0xFFFFFFFFu, pB, 2);
        if (t == 0) {
            const int m = mt * MT + mbase + g;
            out[(size_t)m * Qn + q]       = pA + bias2;
            out[(size_t)(m + 8) * Qn + q] = pB + bias2;
        }
        __syncthreads();   // protect stage s before it is overwritten next iter
        s ^= 1;
    }
}

extern "C" void kernel_launch(void* const* d_in, const int* in_sizes, int n_in,
                              void* d_out, int out_size) {
    const float* x  = (const float*)d_in[0];
    const float* W1 = (const float*)d_in[1];
    const float* b1 = (const float*)d_in[2];
    const float* W2 = (const float*)d_in[3];
    const float* b2 = (const float*)d_in[4];
    float* out = (float*)d_out;

    const int B = in_sizes[0] / Cn;            // 2048
    const int ntiles = (B / MT) * Qn;          // 4096

    static bool configured = false;
    if (!configured) {
        cudaFuncSetAttribute(divenc_kernel,
                             cudaFuncAttributeMaxDynamicSharedMemorySize, SMEM_BYTES);
        configured = true;
    }
    divenc_kernel<<<GRID, 128, SMEM_BYTES>>>(x, W1, b1, W2, b2, out, ntiles);
}